// round 16
// baseline (speedup 1.0000x reference)
#include <cuda_runtime.h>
#include <cstdint>

// PPEG: out[b,0,c] = x[b,0,c] (cls); out[b,1+p,c] = folded 7x7 depthwise conv
// (w7 + pad(w5) + pad(w3) + identity, bias b7+b5+b3) over the 64x64 map.
// R16 = R9 frame + column-streaming: 2-slot rotating column buffer forces
// ptxas to interleave 1 LDG per ~14 FFMA2 (MLP_p1 14 -> 2, kills the
// cross-CTA L1tex queue convoy), and (128,6) caps regs so the buffer
// cannot be widened. Weight rows slide through registers.

#define CH   512
#define HW   64
#define NTOK 4097

typedef unsigned long long ULL;

__device__ float g_weff[49 * CH];   // [tap][channel]
__device__ float g_bsum[CH];

// packed f32x2 FMA (sm_103a FFMA2 — only reachable via PTX)
__device__ __forceinline__ ULL ffma2(ULL a, ULL b, ULL c) {
    ULL d;
    asm("fma.rn.f32x2 %0, %1, %2, %3;" : "=l"(d) : "l"(a), "l"(b), "l"(c));
    return d;
}

// ---------------------------------------------------------------------------
// Kernel 1: weight fold + bias + cls copy, one launch.
__global__ void ppeg_prep(const float* __restrict__ w7, const float* __restrict__ b7,
                          const float* __restrict__ w5, const float* __restrict__ b5,
                          const float* __restrict__ w3, const float* __restrict__ b3,
                          const float* __restrict__ x, float* __restrict__ out) {
    const int bid = blockIdx.x;
    const int tid = threadIdx.x;
    if (bid < 98) {
        const int i = bid * 256 + tid;        // 0 .. 25087 = 512*49
        const int c = i / 49;
        const int t = i % 49;
        const int ky = t / 7, kx = t % 7;
        float v = w7[c * 49 + t];
        if (ky >= 1 && ky <= 5 && kx >= 1 && kx <= 5)
            v += w5[c * 25 + (ky - 1) * 5 + (kx - 1)];
        if (ky >= 2 && ky <= 4 && kx >= 2 && kx <= 4)
            v += w3[c * 9 + (ky - 2) * 3 + (kx - 2)];
        if (t == 24) v += 1.0f;               // identity (residual) term
        g_weff[t * CH + c] = v;
    } else if (bid < 100) {
        const int c = (bid - 98) * 256 + tid;
        g_bsum[c] = b7[c] + b5[c] + b3[c];
    } else {
        const int j = (bid - 100) * 256 + tid;   // cls: 16*512 floats
        const int b = j >> 9;
        const int cc = j & 511;
        const size_t off = (size_t)b * NTOK * CH + cc;
        out[off] = x[off];
    }
}

// ---------------------------------------------------------------------------
// Kernel 2: folded 7x7 depthwise conv, column-streamed.
//   lane   = channel pair (64 ch per block) -> 256B coalesced accesses
//   warp   = 8x2 px subtile; block = 4 warps (2x2) -> 16x4 px tile
//   grid   = (4, 16, 128)
__global__ void __launch_bounds__(128, 6)
ppeg_conv(const float* __restrict__ x, float* __restrict__ out) {
    const int lane = threadIdx.x & 31;
    const int warp = threadIdx.x >> 5;
    const int wx = warp & 1;
    const int wy = warp >> 1;                  // 0..1
    const int x0 = blockIdx.x * 16 + wx * 8;   // RX=8 output cols per thread
    const int y0 = blockIdx.y * 4 + wy * 2;    // RY=2 output rows per thread
    const int b  = blockIdx.z >> 3;
    const int cg = blockIdx.z & 7;
    const int cb = cg * 64;
    const int c  = cb + lane * 2;

    // Stage this channel group's folded weights + bias into SMEM (coalesced).
    __shared__ __align__(16) float sw[49 * 64];
    __shared__ __align__(16) float sb[64];
    #pragma unroll
    for (int i = threadIdx.x; i < 49 * 64; i += 128) {
        const int t  = i >> 6;
        const int cc = i & 63;
        sw[i] = g_weff[t * CH + cb + cc];
    }
    if (threadIdx.x < 64) sb[threadIdx.x] = g_bsum[cb + threadIdx.x];
    __syncthreads();

    const ULL bias = *reinterpret_cast<const ULL*>(&sb[lane * 2]);

    ULL acc[2][8];
    #pragma unroll
    for (int ry = 0; ry < 2; ++ry)
        #pragma unroll
        for (int rx = 0; rx < 8; ++rx)
            acc[ry][rx] = bias;

    const float* xb = x + ((size_t)b * NTOK + 1) * CH + c;
    const float* wbase = xb + ((size_t)(y0 - 3) * HW + (x0 - 3)) * CH;
    const float* swp = &sw[lane * 2];

    // x-interior test: all 14 window cols in [0,64)  (warp-uniform)
    const bool xfull = (x0 >= 3) && (x0 + 10 < HW);

    ULL wk[2][7];                              // sliding weight rows

    #pragma unroll
    for (int riy = 0; riy < 8; ++riy) {
        const int cur = riy & 1;
        const int prv = cur ^ 1;

        if (riy < 7) {                         // load weight row ky = riy once
            #pragma unroll
            for (int kx = 0; kx < 7; ++kx)
                wk[cur][kx] = *reinterpret_cast<const ULL*>(
                    &swp[(riy * 7 + kx) * 64]);
        }

        const int iy = y0 - 3 + riy;
        const bool yok = ((unsigned)iy < (unsigned)HW);
        const bool fast = yok && xfull;
        const float* rowf = wbase + (size_t)riy * (HW * CH);  // fast-path base
        const float* rowb = xb + (size_t)iy * (HW * CH);      // border base

        // column load: col ci of the 14-wide window
        auto ldcol = [&](int ci) -> ULL {
            if (fast)
                return *reinterpret_cast<const ULL*>(&rowf[(size_t)ci * CH]);
            const int xc = x0 - 3 + ci;
            const bool ok = yok && ((unsigned)xc < (unsigned)HW);
            const int xcc = ok ? xc : 0;
            const ULL v = *reinterpret_cast<const ULL*>(&rowb[(size_t)xcc * CH]);
            return ok ? v : 0ULL;
        };

        // column-streaming: 2-slot buffer, load col ci+2 then consume col ci
        ULL buf0 = ldcol(0);
        ULL buf1 = ldcol(1);
        #pragma unroll
        for (int ci = 0; ci < 14; ++ci) {
            const ULL v = (ci & 1) ? buf1 : buf0;
            if (ci + 2 < 14) {
                if (ci & 1) buf1 = ldcol(ci + 2);
                else        buf0 = ldcol(ci + 2);
            }
            // all FMAs consuming window column ci:
            // output col rx uses kx = ci - rx, valid kx in [0,6]
            if (riy <= 6) {                    // ry = 0 uses wk[cur]
                #pragma unroll
                for (int rx = 0; rx < 8; ++rx) {
                    const int kx = ci - rx;
                    if (kx >= 0 && kx <= 6)
                        acc[0][rx] = ffma2(v, wk[cur][kx], acc[0][rx]);
                }
            }
            if (riy >= 1) {                    // ry = 1 uses wk[prv]
                #pragma unroll
                for (int rx = 0; rx < 8; ++rx) {
                    const int kx = ci - rx;
                    if (kx >= 0 && kx <= 6)
                        acc[1][rx] = ffma2(v, wk[prv][kx], acc[1][rx]);
                }
            }
        }
    }

    float* ob = out + ((size_t)b * NTOK + 1) * CH + c;
    #pragma unroll
    for (int ry = 0; ry < 2; ++ry)
        #pragma unroll
        for (int rx = 0; rx < 8; ++rx) {
            const size_t p = (size_t)(y0 + ry) * HW + (x0 + rx);
            *reinterpret_cast<ULL*>(&ob[p * CH]) = acc[ry][rx];
        }
}

// ---------------------------------------------------------------------------
extern "C" void kernel_launch(void* const* d_in, const int* in_sizes, int n_in,
                              void* d_out, int out_size) {
    const float* x  = (const float*)d_in[0];
    const float* w7 = (const float*)d_in[1];
    const float* b7 = (const float*)d_in[2];
    const float* w5 = (const float*)d_in[3];
    const float* b5 = (const float*)d_in[4];
    const float* w3 = (const float*)d_in[5];
    const float* b3 = (const float*)d_in[6];
    float* out = (float*)d_out;

    ppeg_prep<<<132, 256>>>(w7, b7, w5, b5, w3, b3, x, out);
    dim3 grid(4, 16, 16 * 8);                  // 16x4 tiles (R9 shape)
    ppeg_conv<<<grid, 128>>>(x, out);
}

// round 17
// speedup vs baseline: 1.5962x; 1.5962x over previous
#include <cuda_runtime.h>
#include <cstdint>

// PPEG: out[b,0,c] = x[b,0,c] (cls); out[b,1+p,c] = folded 7x7 depthwise conv
// (w7 + pad(w5) + pad(w3) + identity, bias b7+b5+b3) over the 64x64 map.
// R17 = R9 (champion, 88.8us) + __stcs streaming output stores: output is
// write-once, so evict-first stores keep L2 full of the (re-read 3.4x) input.
// Everything else byte-identical to R9. Clean A/B on cache policy.

#define CH   512
#define HW   64
#define NTOK 4097

typedef unsigned long long ULL;

__device__ float g_weff[49 * CH];   // [tap][channel]
__device__ float g_bsum[CH];

// packed f32x2 FMA (sm_103a FFMA2 — only reachable via PTX)
__device__ __forceinline__ ULL ffma2(ULL a, ULL b, ULL c) {
    ULL d;
    asm("fma.rn.f32x2 %0, %1, %2, %3;" : "=l"(d) : "l"(a), "l"(b), "l"(c));
    return d;
}

// ---------------------------------------------------------------------------
// Kernel 1: weight fold + bias + cls copy, one launch.
__global__ void ppeg_prep(const float* __restrict__ w7, const float* __restrict__ b7,
                          const float* __restrict__ w5, const float* __restrict__ b5,
                          const float* __restrict__ w3, const float* __restrict__ b3,
                          const float* __restrict__ x, float* __restrict__ out) {
    const int bid = blockIdx.x;
    const int tid = threadIdx.x;
    if (bid < 98) {
        const int i = bid * 256 + tid;        // 0 .. 25087 = 512*49
        const int c = i / 49;
        const int t = i % 49;
        const int ky = t / 7, kx = t % 7;
        float v = w7[c * 49 + t];
        if (ky >= 1 && ky <= 5 && kx >= 1 && kx <= 5)
            v += w5[c * 25 + (ky - 1) * 5 + (kx - 1)];
        if (ky >= 2 && ky <= 4 && kx >= 2 && kx <= 4)
            v += w3[c * 9 + (ky - 2) * 3 + (kx - 2)];
        if (t == 24) v += 1.0f;               // identity (residual) term
        g_weff[t * CH + c] = v;
    } else if (bid < 100) {
        const int c = (bid - 98) * 256 + tid;
        g_bsum[c] = b7[c] + b5[c] + b3[c];
    } else {
        const int j = (bid - 100) * 256 + tid;   // cls: 16*512 floats
        const int b = j >> 9;
        const int cc = j & 511;
        const size_t off = (size_t)b * NTOK * CH + cc;
        out[off] = x[off];
    }
}

// ---------------------------------------------------------------------------
// Kernel 2: folded 7x7 depthwise conv — R9's exact shape + streaming stores.
//   lane   = channel pair (64 ch per block) -> 256B coalesced accesses
//   warp   = 8x2 px subtile; block = 4 warps (2x2) -> 16x4 px tile
//   grid   = (4, 16, 128); weights+bias staged once to smem
__global__ void __launch_bounds__(128)
ppeg_conv(const float* __restrict__ x, float* __restrict__ out) {
    const int lane = threadIdx.x & 31;
    const int warp = threadIdx.x >> 5;
    const int wx = warp & 1;
    const int wy = warp >> 1;                  // 0..1
    const int x0 = blockIdx.x * 16 + wx * 8;   // RX=8 output cols per thread
    const int y0 = blockIdx.y * 4 + wy * 2;    // RY=2 output rows per thread
    const int b  = blockIdx.z >> 3;
    const int cg = blockIdx.z & 7;
    const int cb = cg * 64;
    const int c  = cb + lane * 2;

    // Stage this channel group's folded weights + bias into SMEM (coalesced).
    __shared__ __align__(16) float sw[49 * 64];
    __shared__ __align__(16) float sb[64];
    #pragma unroll
    for (int i = threadIdx.x; i < 49 * 64; i += 128) {
        const int t  = i >> 6;
        const int cc = i & 63;
        sw[i] = g_weff[t * CH + cb + cc];
    }
    if (threadIdx.x < 64) sb[threadIdx.x] = g_bsum[cb + threadIdx.x];
    __syncthreads();

    const ULL bias = *reinterpret_cast<const ULL*>(&sb[lane * 2]);

    ULL acc[2][8];
    #pragma unroll
    for (int ry = 0; ry < 2; ++ry)
        #pragma unroll
        for (int rx = 0; rx < 8; ++rx)
            acc[ry][rx] = bias;

    const float* xb = x + ((size_t)b * NTOK + 1) * CH + c;
    const float* wbase = xb + ((size_t)(y0 - 3) * HW + (x0 - 3)) * CH;
    const float* swp = &sw[lane * 2];

    // x-interior test: all 14 window cols in [0,64)  (warp-uniform)
    const bool xfull = (x0 >= 3) && (x0 + 10 < HW);

    // Sliding row window: 8 input rows feed the 2 output rows (RY+6).
    #pragma unroll
    for (int riy = 0; riy < 8; ++riy) {
        const int iy = y0 - 3 + riy;
        const bool yok = ((unsigned)iy < (unsigned)HW);

        ULL rw[14];
        if (yok && xfull) {
            // fast path: 14 plain LDG.64 at immediate offsets off one base
            const float* rowp = wbase + (size_t)riy * (HW * CH);
            #pragma unroll
            for (int i = 0; i < 14; ++i)
                rw[i] = *reinterpret_cast<const ULL*>(&rowp[(size_t)i * CH]);
        } else {
            // border path: clamp + select-zero (R2 semantics)
            const float* row = xb + (size_t)iy * HW * CH;
            #pragma unroll
            for (int i = 0; i < 14; ++i) {
                const int xc = x0 - 3 + i;
                rw[i] = (yok && (unsigned)xc < (unsigned)HW)
                      ? *reinterpret_cast<const ULL*>(&row[(size_t)xc * CH])
                      : 0ULL;
            }
        }

        #pragma unroll
        for (int ky = 0; ky < 7; ++ky) {
            const int ry = riy - ky;           // compile-time after full unroll
            if (ry == 0 || ry == 1) {
                #pragma unroll
                for (int kx = 0; kx < 7; ++kx) {
                    const ULL wk = *reinterpret_cast<const ULL*>(
                        &swp[(ky * 7 + kx) * 64]);
                    #pragma unroll
                    for (int rx = 0; rx < 8; ++rx)
                        acc[ry][rx] = ffma2(rw[rx + kx], wk, acc[ry][rx]);
                }
            }
        }
    }

    // Streaming (evict-first) stores: output is never re-read — don't let it
    // evict the re-read input from L2.
    float* ob = out + ((size_t)b * NTOK + 1) * CH + c;
    #pragma unroll
    for (int ry = 0; ry < 2; ++ry)
        #pragma unroll
        for (int rx = 0; rx < 8; ++rx) {
            const size_t p = (size_t)(y0 + ry) * HW + (x0 + rx);
            __stcs(reinterpret_cast<ULL*>(&ob[p * CH]), acc[ry][rx]);
        }
}

// ---------------------------------------------------------------------------
extern "C" void kernel_launch(void* const* d_in, const int* in_sizes, int n_in,
                              void* d_out, int out_size) {
    const float* x  = (const float*)d_in[0];
    const float* w7 = (const float*)d_in[1];
    const float* b7 = (const float*)d_in[2];
    const float* w5 = (const float*)d_in[3];
    const float* b5 = (const float*)d_in[4];
    const float* w3 = (const float*)d_in[5];
    const float* b3 = (const float*)d_in[6];
    float* out = (float*)d_out;

    ppeg_prep<<<132, 256>>>(w7, b7, w5, b5, w3, b3, x, out);
    dim3 grid(4, 16, 16 * 8);                  // 16x4 tiles (R9 shape)
    ppeg_conv<<<grid, 128>>>(x, out);
}